// round 13
// baseline (speedup 1.0000x reference)
#include <cuda_runtime.h>
#include <cuda_bf16.h>
#include <cstdint>

// Problem dims (fixed by the dataset)
#define NN   4096   // nodes
#define EE   8192   // edges
#define INV  512
#define OUTV 512
#define INE  128

// Scratch (allocation-free rule: __device__ globals)
__device__ float g_escale[EE];
// bf16 hi/lo split of T rows: [hi 8192 | lo 8192] per row
__device__ __nv_bfloat16 g_A16[(size_t)NN * 2 * EE];   // 128 MB (scaled by e_scale)
__device__ __nv_bfloat16 g_B16[(size_t)NN * 2 * EE];   // 128 MB (unscaled)
__device__ __nv_bfloat16 g_Chi[(size_t)NN * NN];       // 32 MB
__device__ __nv_bfloat16 g_Clo[(size_t)NN * NN];       // 32 MB
__device__ float g_Hw[(size_t)NN * OUTV];              // 8 MB: Hv @ W
__device__ __nv_bfloat16 g_HwTh[(size_t)OUTV * NN];    // 4 MB: transposed split
__device__ __nv_bfloat16 g_HwTl[(size_t)OUTV * NN];    // 4 MB

// ============================================================================
// sm_80+ PTX helpers (NO arch-specific 'a' features — target is plain sm_103)
// ============================================================================
__device__ __forceinline__ uint32_t smem_u32(const void* p) {
    uint32_t a;
    asm("{ .reg .u64 t; cvta.to.shared.u64 t, %1; cvt.u32.u64 %0, t; }" : "=r"(a) : "l"(p));
    return a;
}

#define SWZ(o) ((o) ^ (((o) >> 3) & 0x70))

#define CP_ASYNC16(saddr, gptr) \
    asm volatile("cp.async.cg.shared.global [%0], [%1], 16;" \
                 :: "r"(saddr), "l"((size_t)__cvta_generic_to_global((const void*)(gptr))))
#define CP_COMMIT() asm volatile("cp.async.commit_group;" ::: "memory")
#define CP_WAIT(n)  asm volatile("cp.async.wait_group " #n ";" ::: "memory")

#define LDSM_X4(r0, r1, r2, r3, addr) \
    asm volatile("ldmatrix.sync.aligned.m8n8.x4.shared.b16 {%0,%1,%2,%3}, [%4];" \
                 : "=r"(r0), "=r"(r1), "=r"(r2), "=r"(r3) : "r"(addr))

#define MMA16816(d, a, b0, b1) \
    asm volatile("mma.sync.aligned.m16n8k16.row.col.f32.bf16.bf16.f32 " \
                 "{%0,%1,%2,%3}, {%4,%5,%6,%7}, {%8,%9}, {%0,%1,%2,%3};" \
                 : "+f"((d)[0]), "+f"((d)[1]), "+f"((d)[2]), "+f"((d)[3]) \
                 : "r"((a)[0]), "r"((a)[1]), "r"((a)[2]), "r"((a)[3]), \
                   "r"(b0), "r"(b1))

__device__ __forceinline__ void bf16_split(float x, uint16_t& h, uint16_t& l) {
    __nv_bfloat16 hb = __float2bfloat16_rn(x);
    __nv_bfloat16 lb = __float2bfloat16_rn(x - __bfloat162float(hb));
    h = __bfloat16_as_ushort(hb);
    l = __bfloat16_as_ushort(lb);
}

// ============================================================================
// 128x128 HMMA tile machinery, 512 threads: 16 warps as 4(m) x 4(n),
// each warp owns a 32x32 sub-tile. SMEM tiles: 128 rows x 128B, SW128.
// ============================================================================
__device__ __forceinline__ void lds_afrag(uint32_t base, int wm, int lane, int ks,
                                          uint32_t a[2][4]) {
#pragma unroll
    for (int mt = 0; mt < 2; ++mt) {
        const int row = wm * 32 + mt * 16 + (lane & 15);
        const int kb  = ks * 32 + ((lane >> 4) * 16);
        LDSM_X4(a[mt][0], a[mt][1], a[mt][2], a[mt][3],
                base + SWZ((uint32_t)(row * 128 + kb)));
    }
}

__device__ __forceinline__ void lds_bfrag(uint32_t base, int wn, int lane, int ks,
                                          uint32_t b[2][4]) {
#pragma unroll
    for (int ng = 0; ng < 2; ++ng) {
        const int nrow = wn * 32 + ng * 16 + ((lane >> 4) * 8) + (lane & 7);
        const int kb   = ks * 32 + (((lane >> 3) & 1) * 16);
        LDSM_X4(b[ng][0], b[ng][1], b[ng][2], b[ng][3],
                base + SWZ((uint32_t)(nrow * 128 + kb)));
    }
}

__device__ __forceinline__ void mma_block(float acc[2][4][4],
                                          uint32_t a[2][4], uint32_t b[2][4]) {
#pragma unroll
    for (int mt = 0; mt < 2; ++mt)
#pragma unroll
        for (int ng = 0; ng < 2; ++ng) {
            MMA16816(acc[mt][2 * ng],     a[mt], b[ng][0], b[ng][1]);
            MMA16816(acc[mt][2 * ng + 1], a[mt], b[ng][2], b[ng][3]);
        }
}

// load one 16KB tile (128 rows x 128B) via cp.async with 512 threads
__device__ __forceinline__ void load_tile512(uint32_t sdst, const char* gsrc,
                                             size_t row_stride, int ldr, int ldk) {
#pragma unroll
    for (int i = 0; i < 2; ++i) {
        const int r = ldr + i * 64;
        CP_ASYNC16(sdst + SWZ((uint32_t)(r * 128 + ldk)),
                   gsrc + (size_t)r * row_stride + ldk);
    }
}

// ---------------------------------------------------------------------------
// e_scale[e] = sum_k H_e[e,k] * p[k]
// ---------------------------------------------------------------------------
__global__ void escale_kernel(const float* __restrict__ He,
                              const float* __restrict__ p) {
    int idx  = blockIdx.x * blockDim.x + threadIdx.x;
    int warp = idx >> 5;
    int lane = idx & 31;
    if (warp >= EE) return;
    float4 v  = reinterpret_cast<const float4*>(He + (size_t)warp * INE)[lane];
    float4 pv = reinterpret_cast<const float4*>(p)[lane];
    float s = v.x * pv.x + v.y * pv.y + v.z * pv.z + v.w * pv.w;
#pragma unroll
    for (int o = 16; o; o >>= 1) s += __shfl_xor_sync(0xFFFFFFFFu, s, o);
    if (lane == 0) g_escale[warp] = s;
}

// ---------------------------------------------------------------------------
// Fused prep kernel (heterogeneous blocks):
//   blocks [0,128):          Hw = Hv @ W  (fp32 register-tiled SGEMM)
//   blocks [128, 128+32768): bf16 hi/lo split of T (scaled and unscaled)
// ---------------------------------------------------------------------------
#define BM 128
#define BN 128
#define BK 16
#define TM 8
#define TN 8
#define SGEMM_BLOCKS 128
#define CONV_BLOCKS  ((int)(((size_t)NN * EE / 4) / 256))   // 32768

__global__ __launch_bounds__(256, 2)
void prep_kernel(const float* __restrict__ Tm, const float* __restrict__ Hv,
                 const float* __restrict__ W) {
    __shared__ float As[BK][BM];
    __shared__ float Bs[BK][BN];

    if (blockIdx.x < SGEMM_BLOCKS) {
        const int bx = blockIdx.x & 3, by = blockIdx.x >> 2;
        const int K = INV, ldn = OUTV;
        const int tid  = threadIdx.x;
        const int tx   = tid & 15;
        const int ty   = tid >> 4;
        const int lrow = tid >> 2;
        const int lcol = (tid & 3) << 2;
        const int brow = tid >> 5;
        const int bcol = (tid & 31) << 2;

        const float* Aptr = Hv + (size_t)(by * BM + lrow) * K + lcol;
        const float* Bptr = W + (size_t)brow * ldn + bx * BN + bcol;

        float acc[TM][TN] = {};

        for (int k0 = 0; k0 < K; k0 += BK) {
#pragma unroll
            for (int r = 0; r < 2; r++) {
                float4 a = *reinterpret_cast<const float4*>(Aptr + (size_t)(r * 64) * K + k0);
                int row = lrow + r * 64;
                As[lcol + 0][row] = a.x;
                As[lcol + 1][row] = a.y;
                As[lcol + 2][row] = a.z;
                As[lcol + 3][row] = a.w;
                float4 bv = *reinterpret_cast<const float4*>(Bptr + (size_t)(k0 + r * 8) * ldn);
                *reinterpret_cast<float4*>(&Bs[brow + r * 8][bcol]) = bv;
            }
            __syncthreads();
#pragma unroll
            for (int k = 0; k < BK; k++) {
                float4 a0 = *reinterpret_cast<const float4*>(&As[k][ty * TM]);
                float4 a1 = *reinterpret_cast<const float4*>(&As[k][ty * TM + 4]);
                float4 b0 = *reinterpret_cast<const float4*>(&Bs[k][tx * TN]);
                float4 b1 = *reinterpret_cast<const float4*>(&Bs[k][tx * TN + 4]);
                float af[8] = {a0.x, a0.y, a0.z, a0.w, a1.x, a1.y, a1.z, a1.w};
                float bf[8] = {b0.x, b0.y, b0.z, b0.w, b1.x, b1.y, b1.z, b1.w};
#pragma unroll
                for (int m = 0; m < TM; m++)
#pragma unroll
                    for (int n = 0; n < TN; n++)
                        acc[m][n] += af[m] * bf[n];
            }
            __syncthreads();
        }

        const int gi0 = by * BM + ty * TM;
        const int gj0 = bx * BN + tx * TN;
#pragma unroll
        for (int m = 0; m < TM; m++)
#pragma unroll
            for (int n = 0; n < TN; n++)
                g_Hw[(size_t)(gi0 + m) * ldn + gj0 + n] = acc[m][n];
    } else {
        size_t v = (size_t)(blockIdx.x - SGEMM_BLOCKS) * 256 + threadIdx.x;
        size_t e = v << 2;
        int k = (int)(e & (EE - 1));
        int r = (int)(e >> 13);
        float4 x  = *reinterpret_cast<const float4*>(Tm + e);
        float4 sv = *reinterpret_cast<const float4*>(g_escale + k);
        float xa[4] = {x.x * sv.x, x.y * sv.y, x.z * sv.z, x.w * sv.w};
        float xb[4] = {x.x, x.y, x.z, x.w};
        uint16_t ah[4], al[4], bh[4], bl[4];
#pragma unroll
        for (int j = 0; j < 4; ++j) {
            bf16_split(xa[j], ah[j], al[j]);
            bf16_split(xb[j], bh[j], bl[j]);
        }
        __nv_bfloat16* Ar = g_A16 + (size_t)r * (2 * EE);
        __nv_bfloat16* Br = g_B16 + (size_t)r * (2 * EE);
        uint2 u;
        u.x = (uint32_t)ah[0] | ((uint32_t)ah[1] << 16);
        u.y = (uint32_t)ah[2] | ((uint32_t)ah[3] << 16);
        *reinterpret_cast<uint2*>(Ar + k) = u;
        u.x = (uint32_t)al[0] | ((uint32_t)al[1] << 16);
        u.y = (uint32_t)al[2] | ((uint32_t)al[3] << 16);
        *reinterpret_cast<uint2*>(Ar + EE + k) = u;
        u.x = (uint32_t)bh[0] | ((uint32_t)bh[1] << 16);
        u.y = (uint32_t)bh[2] | ((uint32_t)bh[3] << 16);
        *reinterpret_cast<uint2*>(Br + k) = u;
        u.x = (uint32_t)bl[0] | ((uint32_t)bl[1] << 16);
        u.y = (uint32_t)bl[2] | ((uint32_t)bl[3] << 16);
        *reinterpret_cast<uint2*>(Br + EE + k) = u;
    }
}

// ---------------------------------------------------------------------------
// Transpose-split Hw [4096,512] -> g_HwTh/g_HwTl [512][4096]
// ---------------------------------------------------------------------------
__global__ void transpose_split_kernel(const float* __restrict__ Hw) {
    __shared__ float tile[32][33];
    const int n0 = blockIdx.x * 32, j0 = blockIdx.y * 32;
    const int tx = threadIdx.x, ty = threadIdx.y;   // 32 x 8
#pragma unroll
    for (int i = 0; i < 4; ++i)
        tile[ty + 8 * i][tx] = Hw[(size_t)(j0 + ty + 8 * i) * OUTV + n0 + tx];
    __syncthreads();
#pragma unroll
    for (int i = 0; i < 4; ++i) {
        const int n = n0 + ty + 8 * i, j = j0 + tx;
        float v = tile[tx][ty + 8 * i];
        uint16_t h, l;
        bf16_split(v, h, l);
        g_HwTh[(size_t)n * NN + j] = __ushort_as_bfloat16(h);
        g_HwTl[(size_t)n * NN + j] = __ushort_as_bfloat16(l);
    }
}

// ---------------------------------------------------------------------------
// HMMA symmetric GEMM (3-term hi/lo split): 128x128 tile, 512 threads,
// 3-stage cp.async pipeline, ONE __syncthreads per chunk, loads issued
// BEFORE the wait (CUTLASS multistage schedule).
// Fused epilogue: Cv = (i==j)? adj[i,i] : 0.5*(M+1)*adj (+ mirror), bf16 split.
// ---------------------------------------------------------------------------
#define ROWB 32768                   // bytes per g_A16/g_B16 row
#define STG  65536                   // stage: Ah|Al|Bh|Bl x 16KB
#define SMEM_PIPE3 (3 * STG)         // 196608

__global__ __launch_bounds__(512, 1)
void symgemm_mma(const float* __restrict__ adjv) {
    extern __shared__ char sm[];
    const uint32_t sb = smem_u32(sm);
    const int tid = threadIdx.x, lane = tid & 31, wid = tid >> 5;
    const int wm = wid >> 2, wn = wid & 3;     // 4 x 4 warp grid

    // triangular tile map: t = bj*(bj+1)/2 + bi, bi <= bj
    int t = blockIdx.x;
    int bj = (int)((sqrtf(8.0f * (float)t + 1.0f) - 1.0f) * 0.5f);
    while ((bj + 1) * (bj + 2) / 2 <= t) ++bj;
    while (bj * (bj + 1) / 2 > t) --bj;
    int bi = t - bj * (bj + 1) / 2;

    const char* Abase = (const char*)g_A16 + (size_t)(bi * 128) * ROWB;
    const char* Bbase = (const char*)g_B16 + (size_t)(bj * 128) * ROWB;

    float acc[2][4][4];
#pragma unroll
    for (int i = 0; i < 2; ++i)
#pragma unroll
        for (int j = 0; j < 4; ++j)
#pragma unroll
            for (int q = 0; q < 4; ++q) acc[i][j][q] = 0.0f;

    const int ldr = tid >> 3;          // 0..63
    const int ldk = (tid & 7) * 16;    // 0..112

    auto load_stage = [&](int s, int c) {
        const uint32_t st = sb + s * STG;
        const int kb = c * 128;
        load_tile512(st,         Abase + kb,         ROWB, ldr, ldk);  // Ah
        load_tile512(st + 16384, Abase + 16384 + kb, ROWB, ldr, ldk);  // Al
        load_tile512(st + 32768, Bbase + kb,         ROWB, ldr, ldk);  // Bh
        load_tile512(st + 49152, Bbase + 16384 + kb, ROWB, ldr, ldk);  // Bl
        CP_COMMIT();
    };

    load_stage(0, 0);

    for (int c = 0; c < 128; ++c) {
        if (c + 1 < 128) { load_stage((c + 1) % 3, c + 1); CP_WAIT(1); }
        else             { CP_WAIT(0); }
        __syncthreads();

        const uint32_t st = sb + (c % 3) * STG;
#pragma unroll
        for (int ks = 0; ks < 4; ++ks) {
            uint32_t ah[2][4], al[2][4], bh[2][4], bl[2][4];
            lds_afrag(st,         wm, lane, ks, ah);
            lds_afrag(st + 16384, wm, lane, ks, al);
            lds_bfrag(st + 32768, wn, lane, ks, bh);
            lds_bfrag(st + 49152, wn, lane, ks, bl);
            mma_block(acc, ah, bh);
            mma_block(acc, ah, bl);
            mma_block(acc, al, bh);
        }
    }
    __syncthreads();   // all MMA reads done before stage memory reuse

    // epilogue: regs -> padded SMEM [128][129] -> fused split-bf16 writes
    float* Msm = reinterpret_cast<float*>(sm);
#pragma unroll
    for (int mt = 0; mt < 2; ++mt) {
        const int m = wm * 32 + mt * 16 + (lane >> 2);
#pragma unroll
        for (int nt = 0; nt < 4; ++nt) {
            const int n = wn * 32 + nt * 8 + 2 * (lane & 3);
            Msm[m * 129 + n]           = acc[mt][nt][0];
            Msm[m * 129 + n + 1]       = acc[mt][nt][1];
            Msm[(m + 8) * 129 + n]     = acc[mt][nt][2];
            Msm[(m + 8) * 129 + n + 1] = acc[mt][nt][3];
        }
    }
    __syncthreads();

    const int i0 = bi * 128, j0 = bj * 128;
    for (int idx = tid; idx < 128 * 64; idx += 512) {
        const int r = idx >> 6, c2 = (idx & 63) * 2;
        const int i = i0 + r, j = j0 + c2;
        float v0 = 0.5f * (Msm[r * 129 + c2] + 1.0f);
        float v1 = 0.5f * (Msm[r * 129 + c2 + 1] + 1.0f);
        v0 = (i == j)     ? adjv[(size_t)i * NN + i] : v0 * adjv[(size_t)i * NN + j];
        v1 = (i == j + 1) ? adjv[(size_t)i * NN + i] : v1 * adjv[(size_t)i * NN + j + 1];
        uint16_t h0, l0, h1, l1;
        bf16_split(v0, h0, l0);
        bf16_split(v1, h1, l1);
        const size_t o = ((size_t)i * NN + j) >> 1;
        reinterpret_cast<uint32_t*>(g_Chi)[o] = (uint32_t)h0 | ((uint32_t)h1 << 16);
        reinterpret_cast<uint32_t*>(g_Clo)[o] = (uint32_t)l0 | ((uint32_t)l1 << 16);
    }
    if (bi != bj) {
        for (int idx = tid; idx < 128 * 64; idx += 512) {
            const int cc = idx >> 6, r2 = (idx & 63) * 2;
            const int i = i0 + r2, j = j0 + cc;
            float v0 = 0.5f * (Msm[r2 * 129 + cc] + 1.0f) * adjv[(size_t)j * NN + i];
            float v1 = 0.5f * (Msm[(r2 + 1) * 129 + cc] + 1.0f) * adjv[(size_t)j * NN + i + 1];
            uint16_t h0, l0, h1, l1;
            bf16_split(v0, h0, l0);
            bf16_split(v1, h1, l1);
            const size_t o = ((size_t)j * NN + i) >> 1;
            reinterpret_cast<uint32_t*>(g_Chi)[o] = (uint32_t)h0 | ((uint32_t)h1 << 16);
            reinterpret_cast<uint32_t*>(g_Clo)[o] = (uint32_t)l0 | ((uint32_t)l1 << 16);
        }
    }
}

// ---------------------------------------------------------------------------
// Final HMMA GEMM: out[4096,512] = (Chi+Clo) @ (HwTh+HwTl)^T + bias
// 3-term split, 512 threads, 3-stage single-sync pipeline, K=4096 -> 64 chunks.
// ---------------------------------------------------------------------------
__global__ __launch_bounds__(512, 1)
void final_mma(float* __restrict__ out, const float* __restrict__ bias) {
    extern __shared__ char sm[];
    const uint32_t sb = smem_u32(sm);
    const int tid = threadIdx.x, lane = tid & 31, wid = tid >> 5;
    const int wm = wid >> 2, wn = wid & 3;

    const int m0 = blockIdx.y * 128, n0 = blockIdx.x * 128;
    const char* Ah = (const char*)g_Chi  + (size_t)m0 * (NN * 2);
    const char* Al = (const char*)g_Clo  + (size_t)m0 * (NN * 2);
    const char* Bh = (const char*)g_HwTh + (size_t)n0 * (NN * 2);
    const char* Bl = (const char*)g_HwTl + (size_t)n0 * (NN * 2);

    float acc[2][4][4];
#pragma unroll
    for (int i = 0; i < 2; ++i)
#pragma unroll
        for (int j = 0; j < 4; ++j)
#pragma unroll
            for (int q = 0; q < 4; ++q) acc[i][j][q] = 0.0f;

    const int ldr = tid >> 3;
    const int ldk = (tid & 7) * 16;

    auto load_stage = [&](int s, int c) {
        const uint32_t st = sb + s * STG;
        const int kb = c * 128;
        load_tile512(st,         Ah + kb, NN * 2, ldr, ldk);
        load_tile512(st + 16384, Al + kb, NN * 2, ldr, ldk);
        load_tile512(st + 32768, Bh + kb, NN * 2, ldr, ldk);
        load_tile512(st + 49152, Bl + kb, NN * 2, ldr, ldk);
        CP_COMMIT();
    };

    load_stage(0, 0);

    for (int c = 0; c < 64; ++c) {
        if (c + 1 < 64) { load_stage((c + 1) % 3, c + 1); CP_WAIT(1); }
        else            { CP_WAIT(0); }
        __syncthreads();

        const uint32_t st = sb + (c % 3) * STG;
#pragma unroll
        for (int ks = 0; ks < 4; ++ks) {
            uint32_t ah[2][4], al[2][4], bh[2][4], bl[2][4];
            lds_afrag(st,         wm, lane, ks, ah);
            lds_afrag(st + 16384, wm, lane, ks, al);
            lds_bfrag(st + 32768, wn, lane, ks, bh);
            lds_bfrag(st + 49152, wn, lane, ks, bl);
            mma_block(acc, ah, bh);
            mma_block(acc, ah, bl);
            mma_block(acc, al, bh);
        }
    }
    __syncthreads();

    // epilogue: regs -> padded SMEM -> coalesced fp32 writes + bias
    float* Msm = reinterpret_cast<float*>(sm);   // [128][129]
#pragma unroll
    for (int mt = 0; mt < 2; ++mt) {
        const int m = wm * 32 + mt * 16 + (lane >> 2);
#pragma unroll
        for (int nt = 0; nt < 4; ++nt) {
            const int n = wn * 32 + nt * 8 + 2 * (lane & 3);
            Msm[m * 129 + n]           = acc[mt][nt][0];
            Msm[m * 129 + n + 1]       = acc[mt][nt][1];
            Msm[(m + 8) * 129 + n]     = acc[mt][nt][2];
            Msm[(m + 8) * 129 + n + 1] = acc[mt][nt][3];
        }
    }
    __syncthreads();

    for (int idx = tid; idx < 128 * 128; idx += 512) {
        const int r = idx >> 7, cc = idx & 127;
        out[(size_t)(m0 + r) * OUTV + n0 + cc] = Msm[r * 129 + cc] + bias[n0 + cc];
    }
}

// ---------------------------------------------------------------------------
// H_e passthrough
// ---------------------------------------------------------------------------
__global__ void copy_kernel(const float* __restrict__ src, float* __restrict__ dst) {
    int i = blockIdx.x * blockDim.x + threadIdx.x;
    reinterpret_cast<float4*>(dst)[i] = reinterpret_cast<const float4*>(src)[i];
}

// ---------------------------------------------------------------------------
extern "C" void kernel_launch(void* const* d_in, const int* in_sizes, int n_in,
                              void* d_out, int out_size) {
    const float* Hv   = (const float*)d_in[0];
    const float* He   = (const float*)d_in[1];
    const float* adjv = (const float*)d_in[3];
    const float* Tm   = (const float*)d_in[4];
    const float* W    = (const float*)d_in[5];
    const float* p    = (const float*)d_in[6];
    const float* bias = (const float*)d_in[7];
    float* out = (float*)d_out;

    float* pHw = nullptr;
    cudaGetSymbolAddress((void**)&pHw, g_Hw);

    cudaFuncSetAttribute(symgemm_mma, cudaFuncAttributeMaxDynamicSharedMemorySize, SMEM_PIPE3);
    cudaFuncSetAttribute(final_mma,   cudaFuncAttributeMaxDynamicSharedMemorySize, SMEM_PIPE3);

    // 1) e_scale = H_e @ p^T
    escale_kernel<<<(EE * 32) / 256, 256>>>(He, p);

    // 2) fused: Hw = Hv @ W  (first 128 blocks)  +  bf16 hi/lo split of T
    prep_kernel<<<SGEMM_BLOCKS + CONV_BLOCKS, 256>>>(Tm, Hv, W);

    // 3) transpose + split Hw -> HwT hi/lo
    transpose_split_kernel<<<dim3(OUTV / 32, NN / 32), dim3(32, 8)>>>(pHw);

    // 4) split C = 0.5*(T diag(s) T^T + 1) * adj_v via HMMA, symmetric tiles
    symgemm_mma<<<(NN / 128) * (NN / 128 + 1) / 2, 512, SMEM_PIPE3>>>(adjv);

    // 5) out = C @ Hw + bias via HMMA
    final_mma<<<dim3(OUTV / 128, NN / 128), 512, SMEM_PIPE3>>>(out, bias);

    // 6) append H_e
    copy_kernel<<<(EE * INE / 4) / 256, 256>>>(He, out + (size_t)NN * OUTV);
}

// round 16
// speedup vs baseline: 1.0276x; 1.0276x over previous
#include <cuda_runtime.h>
#include <cuda_bf16.h>
#include <cstdint>

// Problem dims (fixed by the dataset)
#define NN   4096   // nodes
#define EE   8192   // edges
#define INV  512
#define OUTV 512
#define INE  128

// Scratch (allocation-free rule: __device__ globals)
__device__ float g_escale[EE];
// bf16 hi/lo split of T rows: [hi 8192 | lo 8192] per row
__device__ __nv_bfloat16 g_A16[(size_t)NN * 2 * EE];   // 128 MB (scaled by e_scale)
__device__ __nv_bfloat16 g_B16[(size_t)NN * 2 * EE];   // 128 MB (unscaled)
__device__ __nv_bfloat16 g_Chi[(size_t)NN * NN];       // 32 MB
__device__ __nv_bfloat16 g_Clo[(size_t)NN * NN];       // 32 MB
__device__ float g_Hw[(size_t)NN * OUTV];              // 8 MB: Hv @ W
__device__ __nv_bfloat16 g_HwTh[(size_t)OUTV * NN];    // 4 MB: transposed split
__device__ __nv_bfloat16 g_HwTl[(size_t)OUTV * NN];    // 4 MB

// ============================================================================
// sm_80+ PTX helpers (NO arch-specific 'a' features — target is plain sm_103)
// ============================================================================
__device__ __forceinline__ uint32_t smem_u32(const void* p) {
    uint32_t a;
    asm("{ .reg .u64 t; cvta.to.shared.u64 t, %1; cvt.u32.u64 %0, t; }" : "=r"(a) : "l"(p));
    return a;
}

#define SWZ(o) ((o) ^ (((o) >> 3) & 0x70))

#define CP_ASYNC16(saddr, gptr) \
    asm volatile("cp.async.cg.shared.global [%0], [%1], 16;" \
                 :: "r"(saddr), "l"((size_t)__cvta_generic_to_global((const void*)(gptr))))
#define CP_COMMIT() asm volatile("cp.async.commit_group;" ::: "memory")
#define CP_WAIT(n)  asm volatile("cp.async.wait_group " #n ";" ::: "memory")

#define LDSM_X4(r0, r1, r2, r3, addr) \
    asm volatile("ldmatrix.sync.aligned.m8n8.x4.shared.b16 {%0,%1,%2,%3}, [%4];" \
                 : "=r"(r0), "=r"(r1), "=r"(r2), "=r"(r3) : "r"(addr))

#define MMA16816(d, a, b0, b1) \
    asm volatile("mma.sync.aligned.m16n8k16.row.col.f32.bf16.bf16.f32 " \
                 "{%0,%1,%2,%3}, {%4,%5,%6,%7}, {%8,%9}, {%0,%1,%2,%3};" \
                 : "+f"((d)[0]), "+f"((d)[1]), "+f"((d)[2]), "+f"((d)[3]) \
                 : "r"((a)[0]), "r"((a)[1]), "r"((a)[2]), "r"((a)[3]), \
                   "r"(b0), "r"(b1))

__device__ __forceinline__ void bf16_split(float x, uint16_t& h, uint16_t& l) {
    __nv_bfloat16 hb = __float2bfloat16_rn(x);
    __nv_bfloat16 lb = __float2bfloat16_rn(x - __bfloat162float(hb));
    h = __bfloat16_as_ushort(hb);
    l = __bfloat16_as_ushort(lb);
}

// ============================================================================
// 128x128 HMMA tile machinery (used by final_mma): 8 warps 4(m)x2(n).
// ============================================================================
__device__ __forceinline__ void lds_afrag(uint32_t base, int wm, int lane, int ks,
                                          uint32_t a[2][4]) {
#pragma unroll
    for (int mt = 0; mt < 2; ++mt) {
        const int row = wm * 32 + mt * 16 + (lane & 15);
        const int kb  = ks * 32 + ((lane >> 4) * 16);
        LDSM_X4(a[mt][0], a[mt][1], a[mt][2], a[mt][3],
                base + SWZ((uint32_t)(row * 128 + kb)));
    }
}

__device__ __forceinline__ void lds_bfrag(uint32_t base, int wn, int lane, int ks,
                                          uint32_t b[4][4]) {
#pragma unroll
    for (int ng = 0; ng < 4; ++ng) {
        const int nrow = wn * 64 + ng * 16 + ((lane >> 4) * 8) + (lane & 7);
        const int kb   = ks * 32 + (((lane >> 3) & 1) * 16);
        LDSM_X4(b[ng][0], b[ng][1], b[ng][2], b[ng][3],
                base + SWZ((uint32_t)(nrow * 128 + kb)));
    }
}

__device__ __forceinline__ void mma_block(float acc[2][8][4],
                                          uint32_t a[2][4], uint32_t b[4][4]) {
#pragma unroll
    for (int mt = 0; mt < 2; ++mt)
#pragma unroll
        for (int ng = 0; ng < 4; ++ng) {
            MMA16816(acc[mt][2 * ng],     a[mt], b[ng][0], b[ng][1]);
            MMA16816(acc[mt][2 * ng + 1], a[mt], b[ng][2], b[ng][3]);
        }
}

// load one 16KB tile (128 rows x 128B) via cp.async (256-thread version)
__device__ __forceinline__ void load_tile(uint32_t sdst, const char* gsrc,
                                          size_t row_stride, int ldr, int ldk) {
#pragma unroll
    for (int i = 0; i < 4; ++i) {
        const int r = ldr + i * 32;
        CP_ASYNC16(sdst + SWZ((uint32_t)(r * 128 + ldk)),
                   gsrc + (size_t)r * row_stride + ldk);
    }
}

// ---------------------------------------------------------------------------
// e_scale[e] = sum_k H_e[e,k] * p[k]
// ---------------------------------------------------------------------------
__global__ void escale_kernel(const float* __restrict__ He,
                              const float* __restrict__ p) {
    int idx  = blockIdx.x * blockDim.x + threadIdx.x;
    int warp = idx >> 5;
    int lane = idx & 31;
    if (warp >= EE) return;
    float4 v  = reinterpret_cast<const float4*>(He + (size_t)warp * INE)[lane];
    float4 pv = reinterpret_cast<const float4*>(p)[lane];
    float s = v.x * pv.x + v.y * pv.y + v.z * pv.z + v.w * pv.w;
#pragma unroll
    for (int o = 16; o; o >>= 1) s += __shfl_xor_sync(0xFFFFFFFFu, s, o);
    if (lane == 0) g_escale[warp] = s;
}

// ---------------------------------------------------------------------------
// Fused prep kernel (heterogeneous blocks):
//   blocks [0,128):          Hw = Hv @ W  (fp32 register-tiled SGEMM)
//   blocks [128, 128+32768): bf16 hi/lo split of T (scaled and unscaled)
// Streaming hints: T read once (__ldcs), split outputs written once (__stcs).
// ---------------------------------------------------------------------------
#define BM 128
#define BN 128
#define BK 16
#define TM 8
#define TN 8
#define SGEMM_BLOCKS 128
#define CONV_BLOCKS  ((int)(((size_t)NN * EE / 4) / 256))   // 32768

__global__ __launch_bounds__(256, 2)
void prep_kernel(const float* __restrict__ Tm, const float* __restrict__ Hv,
                 const float* __restrict__ W) {
    __shared__ float As[BK][BM];
    __shared__ float Bs[BK][BN];

    if (blockIdx.x < SGEMM_BLOCKS) {
        const int bx = blockIdx.x & 3, by = blockIdx.x >> 2;
        const int K = INV, ldn = OUTV;
        const int tid  = threadIdx.x;
        const int tx   = tid & 15;
        const int ty   = tid >> 4;
        const int lrow = tid >> 2;
        const int lcol = (tid & 3) << 2;
        const int brow = tid >> 5;
        const int bcol = (tid & 31) << 2;

        const float* Aptr = Hv + (size_t)(by * BM + lrow) * K + lcol;
        const float* Bptr = W + (size_t)brow * ldn + bx * BN + bcol;

        float acc[TM][TN] = {};

        for (int k0 = 0; k0 < K; k0 += BK) {
#pragma unroll
            for (int r = 0; r < 2; r++) {
                float4 a = *reinterpret_cast<const float4*>(Aptr + (size_t)(r * 64) * K + k0);
                int row = lrow + r * 64;
                As[lcol + 0][row] = a.x;
                As[lcol + 1][row] = a.y;
                As[lcol + 2][row] = a.z;
                As[lcol + 3][row] = a.w;
                float4 bv = *reinterpret_cast<const float4*>(Bptr + (size_t)(k0 + r * 8) * ldn);
                *reinterpret_cast<float4*>(&Bs[brow + r * 8][bcol]) = bv;
            }
            __syncthreads();
#pragma unroll
            for (int k = 0; k < BK; k++) {
                float4 a0 = *reinterpret_cast<const float4*>(&As[k][ty * TM]);
                float4 a1 = *reinterpret_cast<const float4*>(&As[k][ty * TM + 4]);
                float4 b0 = *reinterpret_cast<const float4*>(&Bs[k][tx * TN]);
                float4 b1 = *reinterpret_cast<const float4*>(&Bs[k][tx * TN + 4]);
                float af[8] = {a0.x, a0.y, a0.z, a0.w, a1.x, a1.y, a1.z, a1.w};
                float bf[8] = {b0.x, b0.y, b0.z, b0.w, b1.x, b1.y, b1.z, b1.w};
#pragma unroll
                for (int m = 0; m < TM; m++)
#pragma unroll
                    for (int n = 0; n < TN; n++)
                        acc[m][n] += af[m] * bf[n];
            }
            __syncthreads();
        }

        const int gi0 = by * BM + ty * TM;
        const int gj0 = bx * BN + tx * TN;
#pragma unroll
        for (int m = 0; m < TM; m++)
#pragma unroll
            for (int n = 0; n < TN; n++)
                g_Hw[(size_t)(gi0 + m) * ldn + gj0 + n] = acc[m][n];
    } else {
        size_t v = (size_t)(blockIdx.x - SGEMM_BLOCKS) * 256 + threadIdx.x;
        size_t e = v << 2;
        int k = (int)(e & (EE - 1));
        int r = (int)(e >> 13);
        float4 x  = __ldcs(reinterpret_cast<const float4*>(Tm + e));
        float4 sv = *reinterpret_cast<const float4*>(g_escale + k);
        float xa[4] = {x.x * sv.x, x.y * sv.y, x.z * sv.z, x.w * sv.w};
        float xb[4] = {x.x, x.y, x.z, x.w};
        uint16_t ah[4], al[4], bh[4], bl[4];
#pragma unroll
        for (int j = 0; j < 4; ++j) {
            bf16_split(xa[j], ah[j], al[j]);
            bf16_split(xb[j], bh[j], bl[j]);
        }
        __nv_bfloat16* Ar = g_A16 + (size_t)r * (2 * EE);
        __nv_bfloat16* Br = g_B16 + (size_t)r * (2 * EE);
        uint2 u;
        u.x = (uint32_t)ah[0] | ((uint32_t)ah[1] << 16);
        u.y = (uint32_t)ah[2] | ((uint32_t)ah[3] << 16);
        __stcs(reinterpret_cast<uint2*>(Ar + k), u);
        u.x = (uint32_t)al[0] | ((uint32_t)al[1] << 16);
        u.y = (uint32_t)al[2] | ((uint32_t)al[3] << 16);
        __stcs(reinterpret_cast<uint2*>(Ar + EE + k), u);
        u.x = (uint32_t)bh[0] | ((uint32_t)bh[1] << 16);
        u.y = (uint32_t)bh[2] | ((uint32_t)bh[3] << 16);
        __stcs(reinterpret_cast<uint2*>(Br + k), u);
        u.x = (uint32_t)bl[0] | ((uint32_t)bl[1] << 16);
        u.y = (uint32_t)bl[2] | ((uint32_t)bl[3] << 16);
        __stcs(reinterpret_cast<uint2*>(Br + EE + k), u);
    }
}

// ---------------------------------------------------------------------------
// Transpose-split Hw [4096,512] -> g_HwTh/g_HwTl [512][4096]
// ---------------------------------------------------------------------------
__global__ void transpose_split_kernel(const float* __restrict__ Hw) {
    __shared__ float tile[32][33];
    const int n0 = blockIdx.x * 32, j0 = blockIdx.y * 32;
    const int tx = threadIdx.x, ty = threadIdx.y;   // 32 x 8
#pragma unroll
    for (int i = 0; i < 4; ++i)
        tile[ty + 8 * i][tx] = Hw[(size_t)(j0 + ty + 8 * i) * OUTV + n0 + tx];
    __syncthreads();
#pragma unroll
    for (int i = 0; i < 4; ++i) {
        const int n = n0 + ty + 8 * i, j = j0 + tx;
        float v = tile[tx][ty + 8 * i];
        uint16_t h, l;
        bf16_split(v, h, l);
        g_HwTh[(size_t)n * NN + j] = __ushort_as_bfloat16(h);
        g_HwTl[(size_t)n * NN + j] = __ushort_as_bfloat16(l);
    }
}

// ---------------------------------------------------------------------------
// WIDE HMMA symmetric GEMM: 256x128 tile, 512 threads (16 warps, 8m x 2n),
// 3-term hi/lo split, 2-stage cp.async pipeline, B-fragment lookahead.
// Tile order: bj-major (concurrent CTAs share B rows in L2).
// Tiles: bi in [0,16) of 256 rows, bj in [0,32) of 128 cols, bj >= 2*bi.
// ---------------------------------------------------------------------------
#define ROWB 32768                   // bytes per g_A16/g_B16 row
#define STG2 98304                   // stage: Ah(32K)|Al(32K)|Bh(16K)|Bl(16K)
#define SMEM_SYM2 (2 * STG2)         // 196608

__global__ __launch_bounds__(512, 1)
void symgemm_mma2(const float* __restrict__ adjv) {
    extern __shared__ char sm[];
    const uint32_t sb = smem_u32(sm);
    const int tid = threadIdx.x, lane = tid & 31, wid = tid >> 5;
    const int wm = wid >> 1, wn = wid & 1;     // 8 x 2 warp grid

    // bj-major tile decode: for bj in 0..31, n_bi(bj) = min(bj>>1,15)+1
    int rem = blockIdx.x, bj = 0;
    for (;;) {
        const int nbi = (bj >> 1 < 15 ? (bj >> 1) : 15) + 1;
        if (rem < nbi) break;
        rem -= nbi;
        ++bj;
    }
    const int bi = rem;

    const char* Abase = (const char*)g_A16 + (size_t)(bi * 256) * ROWB;
    const char* Bbase = (const char*)g_B16 + (size_t)(bj * 128) * ROWB;

    float acc[2][8][4];
#pragma unroll
    for (int i = 0; i < 2; ++i)
#pragma unroll
        for (int j = 0; j < 8; ++j)
#pragma unroll
            for (int q = 0; q < 4; ++q) acc[i][j][q] = 0.0f;

    const int ldr = tid >> 3;          // 0..63
    const int ldk = (tid & 7) * 16;    // 0..112

    auto load_stage = [&](int s, int c) {
        const uint32_t st = sb + s * STG2;
        const int kb = c * 128;
#pragma unroll
        for (int i = 0; i < 4; ++i) {  // Ah, Al: 256 rows
            const int r = ldr + i * 64;
            const uint32_t so = SWZ((uint32_t)(r * 128 + ldk));
            const char* ga = Abase + (size_t)r * ROWB + kb + ldk;
            CP_ASYNC16(st + so,         ga);
            CP_ASYNC16(st + 32768 + so, ga + 16384);
        }
#pragma unroll
        for (int i = 0; i < 2; ++i) {  // Bh, Bl: 128 rows
            const int r = ldr + i * 64;
            const uint32_t so = SWZ((uint32_t)(r * 128 + ldk));
            const char* gb = Bbase + (size_t)r * ROWB + kb + ldk;
            CP_ASYNC16(st + 65536 + so, gb);
            CP_ASYNC16(st + 81920 + so, gb + 16384);
        }
        CP_COMMIT();
    };

    // B-group fragment loader (group ng of ks; n = wn*64 + ng*16)
    auto load_bgrp = [&](uint32_t st, int ks, int ng, uint32_t bh[4], uint32_t bl[4]) {
        const int nrow = wn * 64 + ng * 16 + ((lane >> 4) * 8) + (lane & 7);
        const int kbb  = ks * 32 + (((lane >> 3) & 1) * 16);
        const uint32_t so = SWZ((uint32_t)(nrow * 128 + kbb));
        LDSM_X4(bh[0], bh[1], bh[2], bh[3], st + 65536 + so);
        LDSM_X4(bl[0], bl[1], bl[2], bl[3], st + 81920 + so);
    };

    load_stage(0, 0);

    for (int c = 0; c < 128; ++c) {
        const int s = c & 1;
        if (c + 1 < 128) { load_stage(s ^ 1, c + 1); CP_WAIT(1); }
        else             { CP_WAIT(0); }
        __syncthreads();

        const uint32_t st = sb + s * STG2;
        uint32_t ah[2][4], al[2][4];
        uint32_t bh[2][4], bl[2][4];

        load_bgrp(st, 0, 0, bh[0], bl[0]);   // prefetch first B group
#pragma unroll
        for (int it = 0; it < 16; ++it) {
            const int ks = it >> 2, ng = it & 3;
            if ((it & 3) == 0) {
                // A fragments for this ks
#pragma unroll
                for (int mt = 0; mt < 2; ++mt) {
                    const int row = wm * 32 + mt * 16 + (lane & 15);
                    const int kb2 = ks * 32 + ((lane >> 4) * 16);
                    const uint32_t so = SWZ((uint32_t)(row * 128 + kb2));
                    LDSM_X4(ah[mt][0], ah[mt][1], ah[mt][2], ah[mt][3], st + so);
                    LDSM_X4(al[mt][0], al[mt][1], al[mt][2], al[mt][3], st + 32768 + so);
                }
            }
            if (it < 15) {
                const int nit = it + 1;
                load_bgrp(st, nit >> 2, nit & 3, bh[nit & 1], bl[nit & 1]);
            }
            const int cur = it & 1;
#pragma unroll
            for (int mt = 0; mt < 2; ++mt) {
                MMA16816(acc[mt][2 * ng],     ah[mt], bh[cur][0], bh[cur][1]);
                MMA16816(acc[mt][2 * ng + 1], ah[mt], bh[cur][2], bh[cur][3]);
                MMA16816(acc[mt][2 * ng],     ah[mt], bl[cur][0], bl[cur][1]);
                MMA16816(acc[mt][2 * ng + 1], ah[mt], bl[cur][2], bl[cur][3]);
                MMA16816(acc[mt][2 * ng],     al[mt], bh[cur][0], bh[cur][1]);
                MMA16816(acc[mt][2 * ng + 1], al[mt], bh[cur][2], bh[cur][3]);
            }
        }
        __syncthreads();
    }

    // epilogue: regs -> padded SMEM [256][129] -> fused split-bf16 writes
    float* Msm = reinterpret_cast<float*>(sm);
#pragma unroll
    for (int mt = 0; mt < 2; ++mt) {
        const int m = wm * 32 + mt * 16 + (lane >> 2);
#pragma unroll
        for (int nt = 0; nt < 8; ++nt) {
            const int n = wn * 64 + nt * 8 + 2 * (lane & 3);
            Msm[m * 129 + n]           = acc[mt][nt][0];
            Msm[m * 129 + n + 1]       = acc[mt][nt][1];
            Msm[(m + 8) * 129 + n]     = acc[mt][nt][2];
            Msm[(m + 8) * 129 + n + 1] = acc[mt][nt][3];
        }
    }
    __syncthreads();

    const int i0 = bi * 256, j0 = bj * 128;
    if (bj >= 2 * bi + 2) {
        // fast path: strictly upper tile (all j > i); packed direct + mirror
        for (int idx = tid; idx < 256 * 64; idx += 512) {
            const int r = idx >> 6, c2 = (idx & 63) * 2;
            const int i = i0 + r, j = j0 + c2;
            const float v0 = 0.5f * (Msm[r * 129 + c2] + 1.0f) * adjv[(size_t)i * NN + j];
            const float v1 = 0.5f * (Msm[r * 129 + c2 + 1] + 1.0f) * adjv[(size_t)i * NN + j + 1];
            uint16_t h0, l0, h1, l1;
            bf16_split(v0, h0, l0);
            bf16_split(v1, h1, l1);
            const size_t o = ((size_t)i * NN + j) >> 1;
            reinterpret_cast<uint32_t*>(g_Chi)[o] = (uint32_t)h0 | ((uint32_t)h1 << 16);
            reinterpret_cast<uint32_t*>(g_Clo)[o] = (uint32_t)l0 | ((uint32_t)l1 << 16);
        }
        for (int idx = tid; idx < 128 * 128; idx += 512) {
            const int cc = idx >> 7, r2 = (idx & 127) * 2;
            const int j = j0 + cc;
            const float v0 = 0.5f * (Msm[r2 * 129 + cc] + 1.0f) * adjv[(size_t)j * NN + i0 + r2];
            const float v1 = 0.5f * (Msm[(r2 + 1) * 129 + cc] + 1.0f) * adjv[(size_t)j * NN + i0 + r2 + 1];
            uint16_t h0, l0, h1, l1;
            bf16_split(v0, h0, l0);
            bf16_split(v1, h1, l1);
            const size_t o = ((size_t)j * NN + i0 + r2) >> 1;
            reinterpret_cast<uint32_t*>(g_Chi)[o] = (uint32_t)h0 | ((uint32_t)h1 << 16);
            reinterpret_cast<uint32_t*>(g_Clo)[o] = (uint32_t)l0 | ((uint32_t)l1 << 16);
        }
    } else {
        // diagonal-straddling tile: scalar path (32 of 272 tiles)
        for (int idx = tid; idx < 256 * 128; idx += 512) {
            const int r = idx >> 7, cc = idx & 127;
            const int i = i0 + r, j = j0 + cc;
            if (j > i) {
                const float Mv = 0.5f * (Msm[r * 129 + cc] + 1.0f);
                uint16_t h, l;
                bf16_split(Mv * adjv[(size_t)i * NN + j], h, l);
                g_Chi[(size_t)i * NN + j] = __ushort_as_bfloat16(h);
                g_Clo[(size_t)i * NN + j] = __ushort_as_bfloat16(l);
                bf16_split(Mv * adjv[(size_t)j * NN + i], h, l);
                g_Chi[(size_t)j * NN + i] = __ushort_as_bfloat16(h);
                g_Clo[(size_t)j * NN + i] = __ushort_as_bfloat16(l);
            } else if (j == i) {
                uint16_t h, l;
                bf16_split(adjv[(size_t)i * NN + i], h, l);
                g_Chi[(size_t)i * NN + i] = __ushort_as_bfloat16(h);
                g_Clo[(size_t)i * NN + i] = __ushort_as_bfloat16(l);
            }
        }
    }
}

// ---------------------------------------------------------------------------
// Final HMMA GEMM: out[4096,512] = (Chi+Clo) @ (HwTh+HwTl)^T + bias
// 3-term split, 2-stage pipeline, K = 4096 -> 64 chunks.
// ---------------------------------------------------------------------------
#define STG  65536
#define SMEM_PIPE (2 * STG)          // 131072

__global__ __launch_bounds__(256, 1)
void final_mma(float* __restrict__ out, const float* __restrict__ bias) {
    extern __shared__ char sm[];
    const uint32_t sb = smem_u32(sm);
    const int tid = threadIdx.x, lane = tid & 31, wid = tid >> 5;
    const int wm = wid >> 1, wn = wid & 1;

    const int m0 = blockIdx.y * 128, n0 = blockIdx.x * 128;
    const char* Ah = (const char*)g_Chi  + (size_t)m0 * (NN * 2);
    const char* Al = (const char*)g_Clo  + (size_t)m0 * (NN * 2);
    const char* Bh = (const char*)g_HwTh + (size_t)n0 * (NN * 2);
    const char* Bl = (const char*)g_HwTl + (size_t)n0 * (NN * 2);

    float acc[2][8][4];
#pragma unroll
    for (int i = 0; i < 2; ++i)
#pragma unroll
        for (int j = 0; j < 8; ++j)
#pragma unroll
            for (int q = 0; q < 4; ++q) acc[i][j][q] = 0.0f;

    const int ldr = tid >> 3;
    const int ldk = (tid & 7) * 16;

    auto load_stage = [&](int s, int c) {
        const uint32_t st = sb + s * STG;
        const int kb = c * 128;
        load_tile(st,         Ah + kb, NN * 2, ldr, ldk);
        load_tile(st + 16384, Al + kb, NN * 2, ldr, ldk);
        load_tile(st + 32768, Bh + kb, NN * 2, ldr, ldk);
        load_tile(st + 49152, Bl + kb, NN * 2, ldr, ldk);
        CP_COMMIT();
    };

    load_stage(0, 0);

    for (int c = 0; c < 64; ++c) {
        const int s = c & 1;
        if (c + 1 < 64) { load_stage(s ^ 1, c + 1); CP_WAIT(1); }
        else            { CP_WAIT(0); }
        __syncthreads();

        const uint32_t st = sb + s * STG;
#pragma unroll
        for (int ks = 0; ks < 4; ++ks) {
            uint32_t ah[2][4], al[2][4], bh[4][4], bl[4][4];
            lds_afrag(st,         wm, lane, ks, ah);
            lds_afrag(st + 16384, wm, lane, ks, al);
            lds_bfrag(st + 32768, wn, lane, ks, bh);
            lds_bfrag(st + 49152, wn, lane, ks, bl);
            mma_block(acc, ah, bh);
            mma_block(acc, ah, bl);
            mma_block(acc, al, bh);
        }
        __syncthreads();
    }

    float* Msm = reinterpret_cast<float*>(sm);   // [128][129]
#pragma unroll
    for (int mt = 0; mt < 2; ++mt) {
        const int m = wm * 32 + mt * 16 + (lane >> 2);
#pragma unroll
        for (int nt = 0; nt < 8; ++nt) {
            const int n = wn * 64 + nt * 8 + 2 * (lane & 3);
            Msm[m * 129 + n]           = acc[mt][nt][0];
            Msm[m * 129 + n + 1]       = acc[mt][nt][1];
            Msm[(m + 8) * 129 + n]     = acc[mt][nt][2];
            Msm[(m + 8) * 129 + n + 1] = acc[mt][nt][3];
        }
    }
    __syncthreads();

    for (int idx = tid; idx < 128 * 128; idx += 256) {
        const int r = idx >> 7, cc = idx & 127;
        out[(size_t)(m0 + r) * OUTV + n0 + cc] = Msm[r * 129 + cc] + bias[n0 + cc];
    }
}

// ---------------------------------------------------------------------------
// H_e passthrough
// ---------------------------------------------------------------------------
__global__ void copy_kernel(const float* __restrict__ src, float* __restrict__ dst) {
    int i = blockIdx.x * blockDim.x + threadIdx.x;
    reinterpret_cast<float4*>(dst)[i] = reinterpret_cast<const float4*>(src)[i];
}

// ---------------------------------------------------------------------------
extern "C" void kernel_launch(void* const* d_in, const int* in_sizes, int n_in,
                              void* d_out, int out_size) {
    const float* Hv   = (const float*)d_in[0];
    const float* He   = (const float*)d_in[1];
    const float* adjv = (const float*)d_in[3];
    const float* Tm   = (const float*)d_in[4];
    const float* W    = (const float*)d_in[5];
    const float* p    = (const float*)d_in[6];
    const float* bias = (const float*)d_in[7];
    float* out = (float*)d_out;

    float* pHw = nullptr;
    cudaGetSymbolAddress((void**)&pHw, g_Hw);

    cudaFuncSetAttribute(symgemm_mma2, cudaFuncAttributeMaxDynamicSharedMemorySize, SMEM_SYM2);
    cudaFuncSetAttribute(final_mma,    cudaFuncAttributeMaxDynamicSharedMemorySize, SMEM_PIPE);

    // 1) e_scale = H_e @ p^T
    escale_kernel<<<(EE * 32) / 256, 256>>>(He, p);

    // 2) fused: Hw = Hv @ W  (first 128 blocks)  +  bf16 hi/lo split of T
    prep_kernel<<<SGEMM_BLOCKS + CONV_BLOCKS, 256>>>(Tm, Hv, W);

    // 3) transpose + split Hw -> HwT hi/lo
    transpose_split_kernel<<<dim3(OUTV / 32, NN / 32), dim3(32, 8)>>>(pHw);

    // 4) split C via wide 256x128 HMMA symmetric tiles (272 CTAs, 512 thr)
    symgemm_mma2<<<272, 512, SMEM_SYM2>>>(adjv);

    // 5) out = C @ Hw + bias via HMMA
    final_mma<<<dim3(OUTV / 128, NN / 128), 256, SMEM_PIPE>>>(out, bias);

    // 6) append H_e
    copy_kernel<<<(EE * INE / 4) / 256, 256>>>(He, out + (size_t)NN * OUTV);
}